// round 11
// baseline (speedup 1.0000x reference)
#include <cuda_runtime.h>
#include <math.h>
#include <stdint.h>

// ---------------- problem constants ----------------
#define BB 64
#define SQ 64
#define SD 512
#define KH 4
#define DD 128
#define NCOLS (BB + KH)
#define INV_T 50.0f
#define SCALE_I8 25.0f

#define THREADS 512
#define NBLOCKS (2048 + BB * KH)   // 2304
#define NCHUNK 4
#define RST 144               // smem row stride bytes: 128 int8 + 16 pad
#define BSTG (128 * RST)      // 18432 bytes per B stage

// smem layout (bytes)
#define SM_A 0                // 128 x 144
#define SM_B 18432            // 2 stages
#define SM_REDP 55296         // uint32[128][4]
#define SM_EXSC 57344         // float[128]
#define SM_LRED 57856         // float[64]
#define SM_FLAG 58112         // int
#define SMEM_TOTAL 58368

// int8 copies of inputs (static device scratch; allocation-free)
__device__ int8_t Qi[BB * SQ * DD];
__device__ int8_t Pi[BB * SD * DD];
__device__ int8_t HNi[BB * KH * SD * DD];
__device__ float g_scores[BB][NCOLS];
__device__ unsigned int g_ctr = 0;

__device__ __forceinline__ uint32_t smem_u32(const void* p) {
    uint32_t a;
    asm("{ .reg .u64 t; cvta.to.shared.u64 t, %1; cvt.u32.u64 %0, t; }" : "=r"(a) : "l"(p));
    return a;
}

#define CP_ASYNC16(dst, src) \
    asm volatile("cp.async.cg.shared.global [%0], [%1], 16;" :: "r"((uint32_t)(dst)), "l"(src))
#define CP_COMMIT asm volatile("cp.async.commit_group;" ::: "memory")

#define LDSM4(r, a) \
    asm volatile("ldmatrix.sync.aligned.m8n8.x4.shared.b16 {%0,%1,%2,%3}, [%4];" \
        : "=r"((r)[0]), "=r"((r)[1]), "=r"((r)[2]), "=r"((r)[3]) : "r"(a))

#define MMAI8(c, a, b0, b1) \
    asm volatile("mma.sync.aligned.m16n8k32.row.col.s32.s8.s8.s32 " \
        "{%0,%1,%2,%3}, {%4,%5,%6,%7}, {%8,%9}, {%0,%1,%2,%3};" \
        : "+r"((c)[0]), "+r"((c)[1]), "+r"((c)[2]), "+r"((c)[3]) \
        : "r"((a)[0]), "r"((a)[1]), "r"((a)[2]), "r"((a)[3]), "r"(b0), "r"(b1))

// pack int score (|v| << 2^20 in practice) with 9-bit doc idx
__device__ __forceinline__ uint32_t packmax_i(int v, uint32_t idx) {
    return (((uint32_t)(v + (1 << 20))) << 9) | idx;
}

// ---------------- fused fp32 -> int8 preconvert (2 elems/thread) ----------------
#define N4_Q (BB * SQ * DD / 4)
#define N4_P (BB * SD * DD / 4)
#define N4_HN (BB * KH * SD * DD / 4)
#define N4_TOT (N4_Q + N4_P + N4_HN)

__device__ __forceinline__ uint32_t quant4(float4 f) {
    int v0 = max(-127, min(127, __float2int_rn(f.x * SCALE_I8)));
    int v1 = max(-127, min(127, __float2int_rn(f.y * SCALE_I8)));
    int v2 = max(-127, min(127, __float2int_rn(f.z * SCALE_I8)));
    int v3 = max(-127, min(127, __float2int_rn(f.w * SCALE_I8)));
    return (uint32_t)(v0 & 0xFF) | ((uint32_t)(v1 & 0xFF) << 8) |
           ((uint32_t)(v2 & 0xFF) << 16) | ((uint32_t)(v3 & 0xFF) << 24);
}

__global__ void cvt_all_kernel(const float4* __restrict__ Q,
                               const float4* __restrict__ P,
                               const float4* __restrict__ HN)
{
    const int t = blockIdx.x * blockDim.x + threadIdx.x;
#pragma unroll
    for (int e = 0; e < 2; ++e) {
        const int i = t * 2 + e;
        if (i >= N4_TOT) return;
        const float4* src; uint32_t* dst; int j;
        if (i < N4_Q)               { src = Q;  dst = (uint32_t*)Qi;  j = i; }
        else if (i < N4_Q + N4_P)   { src = P;  dst = (uint32_t*)Pi;  j = i - N4_Q; }
        else                        { src = HN; dst = (uint32_t*)HNi; j = i - N4_Q - N4_P; }
        dst[j] = quant4(src[j]);
    }
}

__device__ __forceinline__ void load_B_chunk(uint32_t dst_base, const int8_t* src, int tid)
{
#pragma unroll
    for (int j = 0; j < 2; ++j) {
        const int it = tid + j * THREADS;      // 1024 segs: 128 rows x 8 segs of 16B
        const int row = it >> 3, ci = it & 7;
        CP_ASYNC16(dst_base + row * RST + ci * 16, src + row * DD + ci * 16);
    }
}

// ---------------- main kernel: int8 argmax GEMM + 4-cand fp32 rescore + fused loss ----
__global__ __launch_bounds__(THREADS) void maxsim_kernel(
    const float* __restrict__ Q,
    const float* __restrict__ P,
    const float* __restrict__ HN,
    float* __restrict__ out)
{
    extern __shared__ char sm[];
    const uint32_t smb = smem_u32(sm);
    const int tid = threadIdx.x;
    const int wid = tid >> 5;
    const int lid = tid & 31;

    // ---- block -> work mapping ----
    const int8_t* aI; const int8_t* bI;
    const float* aF; const float* bF;
    int qrow0, outcol, validM;
    const int bidx = blockIdx.x;
    if (bidx < 2048) {
        const int mt = bidx >> 6, bp = bidx & 63;
        aI = Qi + (size_t)mt * 128 * DD;  aF = Q + (size_t)mt * 128 * DD;
        bI = Pi + (size_t)bp * SD * DD;   bF = P + (size_t)bp * SD * DD;
        qrow0 = mt * 2; outcol = bp; validM = 128;
    } else {
        const int i = bidx - 2048;
        const int b = i >> 2, k = i & 3;
        aI = Qi + (size_t)b * SQ * DD;    aF = Q + (size_t)b * SQ * DD;
        bI = HNi + (size_t)(b * KH + k) * SD * DD;
        bF = HN + (size_t)(b * KH + k) * SD * DD;
        qrow0 = b; outcol = BB + k; validM = 64;
    }

    // ---- prologue: A (group 0) + B chunks 0,1 ----
#pragma unroll
    for (int j = 0; j < 2; ++j) {
        const int it = tid + j * THREADS;
        const int row = it >> 3, ci = it & 7;
        if (row < validM)
            CP_ASYNC16(smb + SM_A + row * RST + ci * 16, aI + row * DD + ci * 16);
    }
    if (validM == 64) {  // zero upper A rows for HN blocks
        for (int j = tid; j < 576; j += THREADS) {
            const int row = 64 + j / 9, ci = j % 9;
            *(uint4*)(sm + SM_A + row * RST + ci * 16) = make_uint4(0, 0, 0, 0);
        }
    }
    CP_COMMIT;
    load_B_chunk(smb + SM_B, bI, tid);
    CP_COMMIT;
    load_B_chunk(smb + SM_B + BSTG, bI + 128 * DD, tid);
    CP_COMMIT;

    // ---- fragment addressing: 16 warps, 32x32 tiles (wm 0..3, wn 0..3) ----
    const int wm = wid >> 2, wn = wid & 3;
    const int m0 = wm * 32, n0 = wn * 32;
    const int a_r = (lid & 7) + ((lid >> 3) & 1) * 8;
    const uint32_t a_c = ((lid >> 4) & 1) * 16;
    const uint32_t aBase = smb + SM_A + (uint32_t)((m0 + a_r) * RST) + a_c;
    const int b_r = ((lid >> 4) & 1) * 8 + (lid & 7);
    const uint32_t b_c = ((lid >> 3) & 1) * 16;
    const uint32_t bOff0 = (uint32_t)((n0 + b_r) * RST) + b_c;

    int cfr[2][4][4];
#pragma unroll
    for (int mt = 0; mt < 2; ++mt)
#pragma unroll
        for (int nt = 0; nt < 4; ++nt)
#pragma unroll
            for (int i = 0; i < 4; ++i) cfr[mt][nt][i] = 0;

    uint32_t rmp[2][2];
    rmp[0][0] = 0u; rmp[0][1] = 0u; rmp[1][0] = 0u; rmp[1][1] = 0u;

    // ---- main loop ----
#pragma unroll 1
    for (int ch = 0; ch < NCHUNK; ++ch) {
        if (ch < NCHUNK - 1) asm volatile("cp.async.wait_group 1;" ::: "memory");
        else                 asm volatile("cp.async.wait_group 0;" ::: "memory");
        __syncthreads();

        const uint32_t bb = smb + SM_B + (uint32_t)(ch & 1) * BSTG;
#pragma unroll
        for (int kk = 0; kk < 4; ++kk) {
            const uint32_t ko = kk * 32;
            uint32_t af[2][4], bf2[2][4];
            LDSM4(af[0], aBase + ko);
            LDSM4(af[1], aBase + 16 * RST + ko);
            LDSM4(bf2[0], bb + bOff0 + ko);
            LDSM4(bf2[1], bb + bOff0 + 16 * RST + ko);
#pragma unroll
            for (int mt = 0; mt < 2; ++mt) {
                MMAI8(cfr[mt][0], af[mt], bf2[0][0], bf2[0][1]);
                MMAI8(cfr[mt][1], af[mt], bf2[0][2], bf2[0][3]);
                MMAI8(cfr[mt][2], af[mt], bf2[1][0], bf2[1][1]);
                MMAI8(cfr[mt][3], af[mt], bf2[1][2], bf2[1][3]);
            }
        }

        // fold; doc idx = ch*128 + n0 + nt*8 + 2*(lid&3) + j
        const uint32_t base = (uint32_t)(ch * 128 + n0 + 2 * (lid & 3));
#pragma unroll
        for (int mt = 0; mt < 2; ++mt)
#pragma unroll
            for (int nt = 0; nt < 4; ++nt)
#pragma unroll
                for (int h = 0; h < 2; ++h)
#pragma unroll
                    for (int j = 0; j < 2; ++j) {
                        const uint32_t pk = packmax_i(cfr[mt][nt][h * 2 + j], base + nt * 8 + j);
                        rmp[mt][h] = (pk > rmp[mt][h]) ? pk : rmp[mt][h];
                        cfr[mt][nt][h * 2 + j] = 0;
                    }
        __syncthreads();

        if (ch < NCHUNK - 2) {
            load_B_chunk(smb + SM_B + (uint32_t)(ch & 1) * BSTG,
                         bI + (size_t)(ch + 2) * 128 * DD, tid);
            CP_COMMIT;
        }
    }

    // ---- reduce packed max across lane quads -> redp[row][wn] (per-warp group winners) ----
    uint32_t* redp = (uint32_t*)(sm + SM_REDP);
#pragma unroll
    for (int mt = 0; mt < 2; ++mt)
#pragma unroll
        for (int h = 0; h < 2; ++h) {
            uint32_t v = rmp[mt][h];
#pragma unroll
            for (int o = 1; o <= 2; o <<= 1) {
                const uint32_t ov = __shfl_xor_sync(0xffffffffu, v, o);
                v = (ov > v) ? ov : v;
            }
            if ((lid & 3) == 0)
                redp[(m0 + mt * 16 + h * 8 + (lid >> 2)) * 4 + wn] = v;
        }
    __syncthreads();

    // ---- rescore ALL 4 group winners per row in exact fp32; take max ----
    // (kills cross-group argmax swaps from int8 noise -> rel_err margin)
    float* exsc = (float*)(sm + SM_EXSC);
    {
        const int r = tid >> 2, w = tid & 3;         // 128 rows x 4 candidates
        const int rr = (r < validM) ? r : 0;
        const int cand = (int)(redp[rr * 4 + w] & 0x1FFu);
        const float* qp = aF + (size_t)rr * DD;
        const float* dp = bF + (size_t)cand * DD;
        float a0 = 0.f, a1 = 0.f, a2 = 0.f, a3 = 0.f;
#pragma unroll
        for (int j = 0; j < 32; ++j) {
            const float4 qv = __ldg((const float4*)(qp + j * 4));
            const float4 dv = __ldg((const float4*)(dp + j * 4));
            a0 = fmaf(qv.x, dv.x, a0);
            a1 = fmaf(qv.y, dv.y, a1);
            a2 = fmaf(qv.z, dv.z, a2);
            a3 = fmaf(qv.w, dv.w, a3);
        }
        float s = (a0 + a1) + (a2 + a3);
        s = fmaxf(s, __shfl_xor_sync(0xffffffffu, s, 1));
        s = fmaxf(s, __shfl_xor_sync(0xffffffffu, s, 2));
        if (w == 0 && r < validM) exsc[r] = s;
    }
    __syncthreads();

    // ---- sum 64 row scores per batch ----
    if (wid < (validM >> 6) * 2 && (wid & 1) == 0) { }  // (placeholder keeps wid semantics clear)
    if (wid < (validM >> 6)) {
        float s = exsc[wid * 64 + lid] + exsc[wid * 64 + 32 + lid];
#pragma unroll
        for (int o = 16; o > 0; o >>= 1) s += __shfl_down_sync(0xffffffffu, s, o);
        if (lid == 0) g_scores[qrow0 + wid][outcol] = s;
    }

    // ---- fused loss: last block to finish computes the final scalar ----
    __threadfence();
    __syncthreads();
    int* flag = (int*)(sm + SM_FLAG);
    if (tid == 0) {
        const unsigned int old = atomicAdd(&g_ctr, 1u);
        *flag = (((old + 1u) % (unsigned int)gridDim.x) == 0u) ? 1 : 0;
        __threadfence();
    }
    __syncthreads();
    if (*flag) {
        float* lred = (float*)(sm + SM_LRED);
        if (tid < 128) {
            const int q = tid >> 1, part = tid & 1;
            const float* row = &g_scores[q][0];
            const float pos = row[q];
            float m = -INFINITY;
            for (int j = part * 34; j < part * 34 + 34; ++j) m = fmaxf(m, row[j]);
            m = fmaxf(m, __shfl_xor_sync(0xffffffffu, m, 1));
            m = fmaxf(m, pos);
            float sum = (part == 0) ? expf((pos - m) * INV_T) : 0.f;
            for (int j = part * 34; j < part * 34 + 34; ++j)
                sum += expf((row[j] - m) * INV_T);
            sum += __shfl_xor_sync(0xffffffffu, sum, 1);
            if (part == 0) lred[q] = m * INV_T + logf(sum) - pos * INV_T;
        }
        __syncthreads();
        if (tid < 32) {
            float s = lred[tid] + lred[tid + 32];
#pragma unroll
            for (int o = 16; o > 0; o >>= 1) s += __shfl_down_sync(0xffffffffu, s, o);
            if (tid == 0) out[0] = s / (float)BB;
        }
    }
}

extern "C" void kernel_launch(void* const* d_in, const int* in_sizes, int n_in,
                              void* d_out, int out_size)
{
    const float* Q  = (const float*)d_in[0];
    const float* P  = (const float*)d_in[1];
    const float* HN = (const float*)d_in[2];
    (void)in_sizes; (void)n_in; (void)out_size;

    static bool attr_set = false;
    if (!attr_set) {
        cudaFuncSetAttribute(maxsim_kernel,
                             cudaFuncAttributeMaxDynamicSharedMemorySize, SMEM_TOTAL);
        attr_set = true;
    }

    cvt_all_kernel<<<(N4_TOT / 2 + 255) / 256, 256>>>(
        (const float4*)Q, (const float4*)P, (const float4*)HN);
    maxsim_kernel<<<NBLOCKS, THREADS, SMEM_TOTAL>>>(Q, P, HN, (float*)d_out);
}

// round 12
// speedup vs baseline: 1.2130x; 1.2130x over previous
#include <cuda_runtime.h>
#include <math.h>
#include <stdint.h>

// ---------------- problem constants ----------------
#define BB 64
#define SQ 64
#define SD 512
#define KH 4
#define DD 128
#define NCOLS (BB + KH)
#define INV_T 50.0f
#define SCALE_I8 25.0f

#define NBLOCKS (2048 + BB * KH)   // 2304
#define NCHUNK 4
#define RST 144               // smem row stride bytes: 128 int8 + 16 pad
#define BSTG (128 * RST)      // 18432 bytes per B stage

// smem layout (bytes)
#define SM_A 0                // 128 x 144
#define SM_B 18432            // 2 stages
#define SM_REDP 55296         // uint32[128][4]
#define SM_EXSC 57344         // float[128]
#define SM_LRED 57856         // float[64]
#define SM_FLAG 58112         // int
#define SMEM_TOTAL 58368      // x2 CTAs = 116736 <= 227KB

// int8 copies of inputs (static device scratch; allocation-free)
__device__ int8_t Qi[BB * SQ * DD];
__device__ int8_t Pi[BB * SD * DD];
__device__ int8_t HNi[BB * KH * SD * DD];
__device__ float g_scores[BB][NCOLS];
__device__ unsigned int g_ctr = 0;

__device__ __forceinline__ uint32_t smem_u32(const void* p) {
    uint32_t a;
    asm("{ .reg .u64 t; cvta.to.shared.u64 t, %1; cvt.u32.u64 %0, t; }" : "=r"(a) : "l"(p));
    return a;
}

#define CP_ASYNC16(dst, src) \
    asm volatile("cp.async.cg.shared.global [%0], [%1], 16;" :: "r"((uint32_t)(dst)), "l"(src))
#define CP_COMMIT asm volatile("cp.async.commit_group;" ::: "memory")

#define LDSM4(r, a) \
    asm volatile("ldmatrix.sync.aligned.m8n8.x4.shared.b16 {%0,%1,%2,%3}, [%4];" \
        : "=r"((r)[0]), "=r"((r)[1]), "=r"((r)[2]), "=r"((r)[3]) : "r"(a))

#define MMAI8(c, a, b0, b1) \
    asm volatile("mma.sync.aligned.m16n8k32.row.col.s32.s8.s8.s32 " \
        "{%0,%1,%2,%3}, {%4,%5,%6,%7}, {%8,%9}, {%0,%1,%2,%3};" \
        : "+r"((c)[0]), "+r"((c)[1]), "+r"((c)[2]), "+r"((c)[3]) \
        : "r"((a)[0]), "r"((a)[1]), "r"((a)[2]), "r"((a)[3]), "r"(b0), "r"(b1))

// pack int score (|v| << 2^20) with 9-bit doc idx
__device__ __forceinline__ uint32_t packmax_i(int v, uint32_t idx) {
    return (((uint32_t)(v + (1 << 20))) << 9) | idx;
}

// ---------------- fused fp32 -> int8 preconvert ----------------
#define N4_Q (BB * SQ * DD / 4)
#define N4_P (BB * SD * DD / 4)
#define N4_HN (BB * KH * SD * DD / 4)
#define N4_TOT (N4_Q + N4_P + N4_HN)

__global__ void cvt_all_kernel(const float4* __restrict__ Q,
                               const float4* __restrict__ P,
                               const float4* __restrict__ HN)
{
    const int i = blockIdx.x * blockDim.x + threadIdx.x;
    if (i >= N4_TOT) return;
    const float4* src; uint32_t* dst; int j;
    if (i < N4_Q)               { src = Q;  dst = (uint32_t*)Qi;  j = i; }
    else if (i < N4_Q + N4_P)   { src = P;  dst = (uint32_t*)Pi;  j = i - N4_Q; }
    else                        { src = HN; dst = (uint32_t*)HNi; j = i - N4_Q - N4_P; }
    const float4 f = src[j];
    int v0 = max(-127, min(127, __float2int_rn(f.x * SCALE_I8)));
    int v1 = max(-127, min(127, __float2int_rn(f.y * SCALE_I8)));
    int v2 = max(-127, min(127, __float2int_rn(f.z * SCALE_I8)));
    int v3 = max(-127, min(127, __float2int_rn(f.w * SCALE_I8)));
    dst[j] = (uint32_t)(v0 & 0xFF) | ((uint32_t)(v1 & 0xFF) << 8) |
             ((uint32_t)(v2 & 0xFF) << 16) | ((uint32_t)(v3 & 0xFF) << 24);
}

__device__ __forceinline__ void load_B_chunk(uint32_t dst_base, const int8_t* src, int tid)
{
#pragma unroll
    for (int j = 0; j < 4; ++j) {
        const int it = tid + j * 256;          // 1024 segs: 128 rows x 8 segs of 16B
        const int row = it >> 3, ci = it & 7;
        CP_ASYNC16(dst_base + row * RST + ci * 16, src + row * DD + ci * 16);
    }
}

// ---------------- main kernel: R10 structure + occ2 + 4-cand rescore + fused loss ----
__global__ __launch_bounds__(256, 2) void maxsim_kernel(
    const float* __restrict__ Q,
    const float* __restrict__ P,
    const float* __restrict__ HN,
    float* __restrict__ out)
{
    extern __shared__ char sm[];
    const uint32_t smb = smem_u32(sm);
    const int tid = threadIdx.x;
    const int wid = tid >> 5;
    const int lid = tid & 31;

    // ---- block -> work mapping ----
    const int8_t* aI; const int8_t* bI;
    const float* aF; const float* bF;
    int qrow0, outcol, validM;
    const int bidx = blockIdx.x;
    if (bidx < 2048) {
        const int mt = bidx >> 6, bp = bidx & 63;
        aI = Qi + (size_t)mt * 128 * DD;  aF = Q + (size_t)mt * 128 * DD;
        bI = Pi + (size_t)bp * SD * DD;   bF = P + (size_t)bp * SD * DD;
        qrow0 = mt * 2; outcol = bp; validM = 128;
    } else {
        const int i = bidx - 2048;
        const int b = i >> 2, k = i & 3;
        aI = Qi + (size_t)b * SQ * DD;    aF = Q + (size_t)b * SQ * DD;
        bI = HNi + (size_t)(b * KH + k) * SD * DD;
        bF = HN + (size_t)(b * KH + k) * SD * DD;
        qrow0 = b; outcol = BB + k; validM = 64;
    }

    // ---- prologue: A (group 0) + B chunks 0,1 ----
#pragma unroll
    for (int j = 0; j < 4; ++j) {
        const int it = tid + j * 256;
        const int row = it >> 3, ci = it & 7;
        if (row < validM)
            CP_ASYNC16(smb + SM_A + row * RST + ci * 16, aI + row * DD + ci * 16);
    }
    if (validM == 64) {  // zero upper A rows for HN blocks
        for (int j = tid; j < 576; j += 256) {
            const int row = 64 + j / 9, ci = j % 9;
            *(uint4*)(sm + SM_A + row * RST + ci * 16) = make_uint4(0, 0, 0, 0);
        }
    }
    CP_COMMIT;
    load_B_chunk(smb + SM_B, bI, tid);
    CP_COMMIT;
    load_B_chunk(smb + SM_B + BSTG, bI + 128 * DD, tid);
    CP_COMMIT;

    // ---- fragment addressing (R10-validated: 8 warps, 64x32 tiles) ----
    const int wm = wid >> 2, wn = wid & 3;
    const int m0 = wm * 64, n0 = wn * 32;
    const int a_r = (lid & 7) + ((lid >> 3) & 1) * 8;
    const uint32_t a_c = ((lid >> 4) & 1) * 16;
    const uint32_t aBase = smb + SM_A + (uint32_t)((m0 + a_r) * RST) + a_c;
    const int b_r = ((lid >> 4) & 1) * 8 + (lid & 7);
    const uint32_t b_c = ((lid >> 3) & 1) * 16;
    const uint32_t bOff0 = (uint32_t)((n0 + b_r) * RST) + b_c;

    int cfr[4][4][4];
#pragma unroll
    for (int mt = 0; mt < 4; ++mt)
#pragma unroll
        for (int nt = 0; nt < 4; ++nt)
#pragma unroll
            for (int i = 0; i < 4; ++i) cfr[mt][nt][i] = 0;

    uint32_t rmp[4][2];
#pragma unroll
    for (int mt = 0; mt < 4; ++mt) { rmp[mt][0] = 0u; rmp[mt][1] = 0u; }

    // ---- main loop ----
#pragma unroll 1
    for (int ch = 0; ch < NCHUNK; ++ch) {
        if (ch < NCHUNK - 1) asm volatile("cp.async.wait_group 1;" ::: "memory");
        else                 asm volatile("cp.async.wait_group 0;" ::: "memory");
        __syncthreads();

        const uint32_t bb = smb + SM_B + (uint32_t)(ch & 1) * BSTG;
#pragma unroll
        for (int kk = 0; kk < 4; ++kk) {
            const uint32_t ko = kk * 32;
            uint32_t af[4][4], bf2[2][4];
            LDSM4(af[0], aBase + ko);
            LDSM4(af[1], aBase + 16 * RST + ko);
            LDSM4(af[2], aBase + 32 * RST + ko);
            LDSM4(af[3], aBase + 48 * RST + ko);
            LDSM4(bf2[0], bb + bOff0 + ko);
            LDSM4(bf2[1], bb + bOff0 + 16 * RST + ko);
#pragma unroll
            for (int mt = 0; mt < 4; ++mt) {
                MMAI8(cfr[mt][0], af[mt], bf2[0][0], bf2[0][1]);
                MMAI8(cfr[mt][1], af[mt], bf2[0][2], bf2[0][3]);
                MMAI8(cfr[mt][2], af[mt], bf2[1][0], bf2[1][1]);
                MMAI8(cfr[mt][3], af[mt], bf2[1][2], bf2[1][3]);
            }
        }

        // fold; doc idx = ch*128 + n0 + nt*8 + 2*(lid&3) + j
        const uint32_t base = (uint32_t)(ch * 128 + n0 + 2 * (lid & 3));
#pragma unroll
        for (int mt = 0; mt < 4; ++mt)
#pragma unroll
            for (int nt = 0; nt < 4; ++nt)
#pragma unroll
                for (int h = 0; h < 2; ++h)
#pragma unroll
                    for (int j = 0; j < 2; ++j) {
                        const uint32_t pk = packmax_i(cfr[mt][nt][h * 2 + j], base + nt * 8 + j);
                        rmp[mt][h] = (pk > rmp[mt][h]) ? pk : rmp[mt][h];
                        cfr[mt][nt][h * 2 + j] = 0;
                    }
        __syncthreads();

        if (ch < NCHUNK - 2) {
            load_B_chunk(smb + SM_B + (uint32_t)(ch & 1) * BSTG,
                         bI + (size_t)(ch + 2) * 128 * DD, tid);
            CP_COMMIT;
        }
    }

    // ---- reduce packed max across lane quads -> redp[row][wn] ----
    uint32_t* redp = (uint32_t*)(sm + SM_REDP);
#pragma unroll
    for (int mt = 0; mt < 4; ++mt)
#pragma unroll
        for (int h = 0; h < 2; ++h) {
            uint32_t v = rmp[mt][h];
#pragma unroll
            for (int o = 1; o <= 2; o <<= 1) {
                const uint32_t ov = __shfl_xor_sync(0xffffffffu, v, o);
                v = (ov > v) ? ov : v;
            }
            if ((lid & 3) == 0)
                redp[(m0 + mt * 16 + h * 8 + (lid >> 2)) * 4 + wn] = v;
        }
    __syncthreads();

    // ---- phase 2: rescore ALL 4 group winners per row in exact fp32, take max ----
    // (each wn group covers a disjoint set of docs; removes cross-group int8 swaps)
    float* exsc = (float*)(sm + SM_EXSC);
    {
        const int r = tid >> 1, hf = tid & 1;   // 128 rows x 2 threads
        const int rr = (r < validM) ? r : 0;
        const float* qp = aF + (size_t)rr * DD;
        float best = -INFINITY;
#pragma unroll
        for (int wq = 0; wq < 2; ++wq) {
            const int cand = (int)(redp[rr * 4 + hf * 2 + wq] & 0x1FFu);
            const float* dp = bF + (size_t)cand * DD;
            float a0 = 0.f, a1 = 0.f, a2 = 0.f, a3 = 0.f;
#pragma unroll
            for (int j = 0; j < 32; ++j) {
                const float4 qv = __ldg((const float4*)(qp + j * 4));
                const float4 dv = __ldg((const float4*)(dp + j * 4));
                a0 = fmaf(qv.x, dv.x, a0);
                a1 = fmaf(qv.y, dv.y, a1);
                a2 = fmaf(qv.z, dv.z, a2);
                a3 = fmaf(qv.w, dv.w, a3);
            }
            best = fmaxf(best, (a0 + a1) + (a2 + a3));
        }
        best = fmaxf(best, __shfl_xor_sync(0xffffffffu, best, 1));
        if (hf == 0 && r < validM) exsc[r] = best;
    }
    __syncthreads();

    // ---- sum 64 row scores per batch ----
    if (wid < (validM >> 6)) {
        float s = exsc[wid * 64 + lid] + exsc[wid * 64 + 32 + lid];
#pragma unroll
        for (int o = 16; o > 0; o >>= 1) s += __shfl_down_sync(0xffffffffu, s, o);
        if (lid == 0) g_scores[qrow0 + wid][outcol] = s;
    }

    // ---- fused loss: last block to finish computes the final scalar ----
    __threadfence();
    __syncthreads();
    int* flag = (int*)(sm + SM_FLAG);
    if (tid == 0) {
        const unsigned int old = atomicAdd(&g_ctr, 1u);
        *flag = (((old + 1u) % (unsigned int)gridDim.x) == 0u) ? 1 : 0;
        __threadfence();
    }
    __syncthreads();
    if (*flag) {
        float* lred = (float*)(sm + SM_LRED);
        if (tid < 128) {
            const int q = tid >> 1, part = tid & 1;
            const float* row = &g_scores[q][0];
            const float pos = row[q];
            float m = -INFINITY;
            for (int j = part * 34; j < part * 34 + 34; ++j) m = fmaxf(m, row[j]);
            m = fmaxf(m, __shfl_xor_sync(0xffffffffu, m, 1));
            m = fmaxf(m, pos);
            float sum = (part == 0) ? expf((pos - m) * INV_T) : 0.f;
            for (int j = part * 34; j < part * 34 + 34; ++j)
                sum += expf((row[j] - m) * INV_T);
            sum += __shfl_xor_sync(0xffffffffu, sum, 1);
            if (part == 0) lred[q] = m * INV_T + logf(sum) - pos * INV_T;
        }
        __syncthreads();
        if (tid < 32) {
            float s = lred[tid] + lred[tid + 32];
#pragma unroll
            for (int o = 16; o > 0; o >>= 1) s += __shfl_down_sync(0xffffffffu, s, o);
            if (tid == 0) out[0] = s / (float)BB;
        }
    }
}

extern "C" void kernel_launch(void* const* d_in, const int* in_sizes, int n_in,
                              void* d_out, int out_size)
{
    const float* Q  = (const float*)d_in[0];
    const float* P  = (const float*)d_in[1];
    const float* HN = (const float*)d_in[2];
    (void)in_sizes; (void)n_in; (void)out_size;

    static bool attr_set = false;
    if (!attr_set) {
        cudaFuncSetAttribute(maxsim_kernel,
                             cudaFuncAttributeMaxDynamicSharedMemorySize, SMEM_TOTAL);
        attr_set = true;
    }

    cvt_all_kernel<<<(N4_TOT + 255) / 256, 256>>>(
        (const float4*)Q, (const float4*)P, (const float4*)HN);
    maxsim_kernel<<<NBLOCKS, 256, SMEM_TOTAL>>>(Q, P, HN, (float*)d_out);
}

// round 13
// speedup vs baseline: 1.3663x; 1.1264x over previous
#include <cuda_runtime.h>
#include <math.h>
#include <stdint.h>
#include <limits.h>

// ---------------- problem constants ----------------
#define BB 64
#define SQ 64
#define SD 512
#define KH 4
#define DD 128
#define NCOLS (BB + KH)
#define INV_T 50.0f
#define SCALE_I8 25.0f

#define NBLOCKS (2048 + BB * KH)   // 2304
#define NCHUNK 4
#define RST 144               // smem row stride bytes: 128 int8 + 16 pad
#define BSTG (128 * RST)      // 18432 bytes per B stage

// smem layout (bytes)
#define SM_A 0                // 128 x 144
#define SM_B 18432            // 2 stages
#define SM_REDP 55296         // int32[128][4]
#define SM_EXSC 57344         // float[128]
#define SM_LRED 57856         // float[64]
#define SM_FLAG 58112         // int
#define SMEM_TOTAL 58368

// rescore threshold: 1024 int units ~ 9 sigma of int8 quantization noise
#define RES_DELTA (1024 << 9)

// int8 copies of inputs (static device scratch; allocation-free)
__device__ int8_t Qi[BB * SQ * DD];
__device__ int8_t Pi[BB * SD * DD];
__device__ int8_t HNi[BB * KH * SD * DD];
__device__ float g_scores[BB][NCOLS];
__device__ unsigned int g_ctr = 0;

__device__ __forceinline__ uint32_t smem_u32(const void* p) {
    uint32_t a;
    asm("{ .reg .u64 t; cvta.to.shared.u64 t, %1; cvt.u32.u64 %0, t; }" : "=r"(a) : "l"(p));
    return a;
}

#define CP_ASYNC16(dst, src) \
    asm volatile("cp.async.cg.shared.global [%0], [%1], 16;" :: "r"((uint32_t)(dst)), "l"(src))
#define CP_COMMIT asm volatile("cp.async.commit_group;" ::: "memory")

#define LDSM4(r, a) \
    asm volatile("ldmatrix.sync.aligned.m8n8.x4.shared.b16 {%0,%1,%2,%3}, [%4];" \
        : "=r"((r)[0]), "=r"((r)[1]), "=r"((r)[2]), "=r"((r)[3]) : "r"(a))

#define MMAI8(c, a, b0, b1) \
    asm volatile("mma.sync.aligned.m16n8k32.row.col.s32.s8.s8.s32 " \
        "{%0,%1,%2,%3}, {%4,%5,%6,%7}, {%8,%9}, {%0,%1,%2,%3};" \
        : "+r"((c)[0]), "+r"((c)[1]), "+r"((c)[2]), "+r"((c)[3]) \
        : "r"((a)[0]), "r"((a)[1]), "r"((a)[2]), "r"((a)[3]), "r"(b0), "r"(b1))

// monotone pack: v*512 + idx + 2^29 (IMAD); idx = pk & 511 (offsets are 0 mod 512)
__device__ __forceinline__ int packmax_i(int v, int idx) {
    return v * 512 + idx + (1 << 29);
}

// ---------------- fused fp32 -> int8 preconvert ----------------
#define N4_Q (BB * SQ * DD / 4)
#define N4_P (BB * SD * DD / 4)
#define N4_HN (BB * KH * SD * DD / 4)
#define N4_TOT (N4_Q + N4_P + N4_HN)

__global__ void cvt_all_kernel(const float4* __restrict__ Q,
                               const float4* __restrict__ P,
                               const float4* __restrict__ HN)
{
    const int i = blockIdx.x * blockDim.x + threadIdx.x;
    if (i >= N4_TOT) return;
    const float4* src; uint32_t* dst; int j;
    if (i < N4_Q)               { src = Q;  dst = (uint32_t*)Qi;  j = i; }
    else if (i < N4_Q + N4_P)   { src = P;  dst = (uint32_t*)Pi;  j = i - N4_Q; }
    else                        { src = HN; dst = (uint32_t*)HNi; j = i - N4_Q - N4_P; }
    const float4 f = src[j];
    int v0 = max(-127, min(127, __float2int_rn(f.x * SCALE_I8)));
    int v1 = max(-127, min(127, __float2int_rn(f.y * SCALE_I8)));
    int v2 = max(-127, min(127, __float2int_rn(f.z * SCALE_I8)));
    int v3 = max(-127, min(127, __float2int_rn(f.w * SCALE_I8)));
    dst[j] = (uint32_t)(v0 & 0xFF) | ((uint32_t)(v1 & 0xFF) << 8) |
             ((uint32_t)(v2 & 0xFF) << 16) | ((uint32_t)(v3 & 0xFF) << 24);
}

__device__ __forceinline__ void load_B_chunk(uint32_t dst_base, const int8_t* src, int tid)
{
#pragma unroll
    for (int j = 0; j < 4; ++j) {
        const int it = tid + j * 256;          // 1024 segs: 128 rows x 8 segs of 16B
        const int row = it >> 3, ci = it & 7;
        CP_ASYNC16(dst_base + row * RST + ci * 16, src + row * DD + ci * 16);
    }
}

// ---------------- main kernel (R10 structure + IMAD fold + cond. rescore + fused loss) ----
__global__ __launch_bounds__(256) void maxsim_kernel(
    const float* __restrict__ Q,
    const float* __restrict__ P,
    const float* __restrict__ HN,
    float* __restrict__ out)
{
    extern __shared__ char sm[];
    const uint32_t smb = smem_u32(sm);
    const int tid = threadIdx.x;
    const int wid = tid >> 5;
    const int lid = tid & 31;

    // ---- block -> work mapping ----
    const int8_t* aI; const int8_t* bI;
    const float* aF; const float* bF;
    int qrow0, outcol, validM;
    const int bidx = blockIdx.x;
    if (bidx < 2048) {
        const int mt = bidx >> 6, bp = bidx & 63;
        aI = Qi + (size_t)mt * 128 * DD;  aF = Q + (size_t)mt * 128 * DD;
        bI = Pi + (size_t)bp * SD * DD;   bF = P + (size_t)bp * SD * DD;
        qrow0 = mt * 2; outcol = bp; validM = 128;
    } else {
        const int i = bidx - 2048;
        const int b = i >> 2, k = i & 3;
        aI = Qi + (size_t)b * SQ * DD;    aF = Q + (size_t)b * SQ * DD;
        bI = HNi + (size_t)(b * KH + k) * SD * DD;
        bF = HN + (size_t)(b * KH + k) * SD * DD;
        qrow0 = b; outcol = BB + k; validM = 64;
    }

    // ---- prologue: A (group 0) + B chunks 0,1 ----
#pragma unroll
    for (int j = 0; j < 4; ++j) {
        const int it = tid + j * 256;
        const int row = it >> 3, ci = it & 7;
        if (row < validM)
            CP_ASYNC16(smb + SM_A + row * RST + ci * 16, aI + row * DD + ci * 16);
    }
    if (validM == 64) {  // zero upper A rows for HN blocks
        for (int j = tid; j < 576; j += 256) {
            const int row = 64 + j / 9, ci = j % 9;
            *(uint4*)(sm + SM_A + row * RST + ci * 16) = make_uint4(0, 0, 0, 0);
        }
    }
    CP_COMMIT;
    load_B_chunk(smb + SM_B, bI, tid);
    CP_COMMIT;
    load_B_chunk(smb + SM_B + BSTG, bI + 128 * DD, tid);
    CP_COMMIT;

    // ---- fragment addressing (R10-validated) ----
    const int wm = wid >> 2, wn = wid & 3;
    const int m0 = wm * 64, n0 = wn * 32;
    const int a_r = (lid & 7) + ((lid >> 3) & 1) * 8;
    const uint32_t a_c = ((lid >> 4) & 1) * 16;
    const uint32_t aBase = smb + SM_A + (uint32_t)((m0 + a_r) * RST) + a_c;
    const int b_r = ((lid >> 4) & 1) * 8 + (lid & 7);
    const uint32_t b_c = ((lid >> 3) & 1) * 16;
    const uint32_t bOff0 = (uint32_t)((n0 + b_r) * RST) + b_c;

    int cfr[4][4][4];
#pragma unroll
    for (int mt = 0; mt < 4; ++mt)
#pragma unroll
        for (int nt = 0; nt < 4; ++nt)
#pragma unroll
            for (int i = 0; i < 4; ++i) cfr[mt][nt][i] = 0;

    int rmp[4][2];
#pragma unroll
    for (int mt = 0; mt < 4; ++mt) { rmp[mt][0] = INT_MIN; rmp[mt][1] = INT_MIN; }

    // ---- main loop ----
#pragma unroll 1
    for (int ch = 0; ch < NCHUNK; ++ch) {
        if (ch < NCHUNK - 1) asm volatile("cp.async.wait_group 1;" ::: "memory");
        else                 asm volatile("cp.async.wait_group 0;" ::: "memory");
        __syncthreads();

        const uint32_t bb = smb + SM_B + (uint32_t)(ch & 1) * BSTG;
#pragma unroll
        for (int kk = 0; kk < 4; ++kk) {
            const uint32_t ko = kk * 32;
            uint32_t af[4][4], bf2[2][4];
            LDSM4(af[0], aBase + ko);
            LDSM4(af[1], aBase + 16 * RST + ko);
            LDSM4(af[2], aBase + 32 * RST + ko);
            LDSM4(af[3], aBase + 48 * RST + ko);
            LDSM4(bf2[0], bb + bOff0 + ko);
            LDSM4(bf2[1], bb + bOff0 + 16 * RST + ko);
#pragma unroll
            for (int mt = 0; mt < 4; ++mt) {
                MMAI8(cfr[mt][0], af[mt], bf2[0][0], bf2[0][1]);
                MMAI8(cfr[mt][1], af[mt], bf2[0][2], bf2[0][3]);
                MMAI8(cfr[mt][2], af[mt], bf2[1][0], bf2[1][1]);
                MMAI8(cfr[mt][3], af[mt], bf2[1][2], bf2[1][3]);
            }
        }

        // fold (IMAD pack + signed max); doc idx = ch*128 + n0 + nt*8 + 2*(lid&3) + j
        const int base = ch * 128 + n0 + 2 * (lid & 3);
#pragma unroll
        for (int mt = 0; mt < 4; ++mt)
#pragma unroll
            for (int nt = 0; nt < 4; ++nt)
#pragma unroll
                for (int h = 0; h < 2; ++h)
#pragma unroll
                    for (int j = 0; j < 2; ++j) {
                        const int pk = packmax_i(cfr[mt][nt][h * 2 + j], base + nt * 8 + j);
                        rmp[mt][h] = max(rmp[mt][h], pk);
                        cfr[mt][nt][h * 2 + j] = 0;
                    }
        __syncthreads();

        if (ch < NCHUNK - 2) {
            load_B_chunk(smb + SM_B + (uint32_t)(ch & 1) * BSTG,
                         bI + (size_t)(ch + 2) * 128 * DD, tid);
            CP_COMMIT;
        }
    }

    // ---- reduce packed max across lane quads -> redp[row][wn] ----
    int* redp = (int*)(sm + SM_REDP);
#pragma unroll
    for (int mt = 0; mt < 4; ++mt)
#pragma unroll
        for (int h = 0; h < 2; ++h) {
            int v = rmp[mt][h];
#pragma unroll
            for (int o = 1; o <= 2; o <<= 1)
                v = max(v, __shfl_xor_sync(0xffffffffu, v, o));
            if ((lid & 3) == 0)
                redp[(m0 + mt * 16 + h * 8 + (lid >> 2)) * 4 + wn] = v;
        }
    __syncthreads();

    // ---- phase 2: conditional exact fp32 rescore of group winners ----
    // Rescore candidate only if its int8 score is within RES_DELTA of the row best
    // (sound: quantization noise sigma ~116 int units << 1024). Winner always rescored.
    float* exsc = (float*)(sm + SM_EXSC);
    {
        const int r = tid >> 1, hf = tid & 1;   // 128 rows x 2 threads
        const int rr = (r < validM) ? r : 0;
        const int p0 = redp[rr * 4 + 0], p1 = redp[rr * 4 + 1];
        const int p2 = redp[rr * 4 + 2], p3 = redp[rr * 4 + 3];
        const int bestp = max(max(p0, p1), max(p2, p3));
        const float* qp = aF + (size_t)rr * DD;
        float best = -INFINITY;
#pragma unroll
        for (int wq = 0; wq < 2; ++wq) {
            const int pk = (hf == 0) ? (wq == 0 ? p0 : p1) : (wq == 0 ? p2 : p3);
            if (bestp - pk <= RES_DELTA) {
                const int cand = (int)((uint32_t)pk & 511u);
                const float* dp = bF + (size_t)cand * DD;
                float a0 = 0.f, a1 = 0.f, a2 = 0.f, a3 = 0.f;
#pragma unroll
                for (int j = 0; j < 32; ++j) {
                    const float4 qv = __ldg((const float4*)(qp + j * 4));
                    const float4 dv = __ldg((const float4*)(dp + j * 4));
                    a0 = fmaf(qv.x, dv.x, a0);
                    a1 = fmaf(qv.y, dv.y, a1);
                    a2 = fmaf(qv.z, dv.z, a2);
                    a3 = fmaf(qv.w, dv.w, a3);
                }
                best = fmaxf(best, (a0 + a1) + (a2 + a3));
            }
        }
        best = fmaxf(best, __shfl_xor_sync(0xffffffffu, best, 1));
        if (hf == 0 && r < validM) exsc[r] = best;
    }
    __syncthreads();

    // ---- sum 64 row scores per batch ----
    if (wid < (validM >> 6)) {
        float s = exsc[wid * 64 + lid] + exsc[wid * 64 + 32 + lid];
#pragma unroll
        for (int o = 16; o > 0; o >>= 1) s += __shfl_down_sync(0xffffffffu, s, o);
        if (lid == 0) g_scores[qrow0 + wid][outcol] = s;
    }

    // ---- fused loss: last block to finish computes the final scalar ----
    __threadfence();
    __syncthreads();
    int* flag = (int*)(sm + SM_FLAG);
    if (tid == 0) {
        const unsigned int old = atomicAdd(&g_ctr, 1u);
        *flag = (((old + 1u) % (unsigned int)gridDim.x) == 0u) ? 1 : 0;
        __threadfence();
    }
    __syncthreads();
    if (*flag) {
        float* lred = (float*)(sm + SM_LRED);
        if (tid < 128) {
            const int q = tid >> 1, part = tid & 1;
            const float* row = &g_scores[q][0];
            const float pos = row[q];
            float m = -INFINITY;
            for (int j = part * 34; j < part * 34 + 34; ++j) m = fmaxf(m, row[j]);
            m = fmaxf(m, __shfl_xor_sync(0xffffffffu, m, 1));
            m = fmaxf(m, pos);
            float sum = (part == 0) ? expf((pos - m) * INV_T) : 0.f;
            for (int j = part * 34; j < part * 34 + 34; ++j)
                sum += expf((row[j] - m) * INV_T);
            sum += __shfl_xor_sync(0xffffffffu, sum, 1);
            if (part == 0) lred[q] = m * INV_T + logf(sum) - pos * INV_T;
        }
        __syncthreads();
        if (tid < 32) {
            float s = lred[tid] + lred[tid + 32];
#pragma unroll
            for (int o = 16; o > 0; o >>= 1) s += __shfl_down_sync(0xffffffffu, s, o);
            if (tid == 0) out[0] = s / (float)BB;
        }
    }
}

extern "C" void kernel_launch(void* const* d_in, const int* in_sizes, int n_in,
                              void* d_out, int out_size)
{
    const float* Q  = (const float*)d_in[0];
    const float* P  = (const float*)d_in[1];
    const float* HN = (const float*)d_in[2];
    (void)in_sizes; (void)n_in; (void)out_size;

    static bool attr_set = false;
    if (!attr_set) {
        cudaFuncSetAttribute(maxsim_kernel,
                             cudaFuncAttributeMaxDynamicSharedMemorySize, SMEM_TOTAL);
        attr_set = true;
    }

    cvt_all_kernel<<<(N4_TOT + 255) / 256, 256>>>(
        (const float4*)Q, (const float4*)P, (const float4*)HN);
    maxsim_kernel<<<NBLOCKS, 256, SMEM_TOTAL>>>(Q, P, HN, (float*)d_out);
}

// round 14
// speedup vs baseline: 2.1020x; 1.5384x over previous
#include <cuda_runtime.h>
#include <math.h>
#include <stdint.h>

// ---------------- problem constants ----------------
#define BB 64
#define SQ 64
#define SD 512
#define KH 4
#define DD 128
#define NCOLS (BB + KH)
#define INV_T 50.0f
#define SCALE_I8 25.0f

#define NCHUNK 4
#define RST 144               // smem row stride bytes: 128 int8 + 16 pad
#define BSTG (128 * RST)      // 18432 bytes per B chunk

// smem layout (bytes): A + 4 resident B chunks
#define SM_A 0                // 18432
#define SM_B 18432            // 4 x 18432 = 73728
#define SM_REDP 92160         // uint32[128][4]
#define SM_WIDX 94208         // int[128]
#define SM_EXSC 94720         // float[128]
#define SMEM_TOTAL 95232

// int8 copies of inputs (static device scratch; allocation-free)
__device__ int8_t Qi[BB * SQ * DD];
__device__ int8_t Pi[BB * SD * DD];
__device__ int8_t HNi[BB * KH * SD * DD];
__device__ float g_scores[BB][NCOLS];

__device__ __forceinline__ uint32_t smem_u32(const void* p) {
    uint32_t a;
    asm("{ .reg .u64 t; cvta.to.shared.u64 t, %1; cvt.u32.u64 %0, t; }" : "=r"(a) : "l"(p));
    return a;
}

#define CP_ASYNC16(dst, src) \
    asm volatile("cp.async.cg.shared.global [%0], [%1], 16;" :: "r"((uint32_t)(dst)), "l"(src))
#define CP_COMMIT asm volatile("cp.async.commit_group;" ::: "memory")
#define CP_WAIT(n) asm volatile("cp.async.wait_group %0;" :: "n"(n) : "memory")

#define LDSM4(r, a) \
    asm volatile("ldmatrix.sync.aligned.m8n8.x4.shared.b16 {%0,%1,%2,%3}, [%4];" \
        : "=r"((r)[0]), "=r"((r)[1]), "=r"((r)[2]), "=r"((r)[3]) : "r"(a))

#define MMAI8(c, a, b0, b1) \
    asm volatile("mma.sync.aligned.m16n8k32.row.col.s32.s8.s8.s32 " \
        "{%0,%1,%2,%3}, {%4,%5,%6,%7}, {%8,%9}, {%0,%1,%2,%3};" \
        : "+r"((c)[0]), "+r"((c)[1]), "+r"((c)[2]), "+r"((c)[3]) \
        : "r"((a)[0]), "r"((a)[1]), "r"((a)[2]), "r"((a)[3]), "r"(b0), "r"(b1))

// pack int score (|v| << 2^20) with 9-bit doc idx  (R10-validated)
__device__ __forceinline__ uint32_t packmax_i(int v, uint32_t idx) {
    return (((uint32_t)(v + (1 << 20))) << 9) | idx;
}

// ---------------- fused fp32 -> int8 preconvert (R10-identical) ----------------
#define N4_Q (BB * SQ * DD / 4)
#define N4_P (BB * SD * DD / 4)
#define N4_HN (BB * KH * SD * DD / 4)
#define N4_TOT (N4_Q + N4_P + N4_HN)

__global__ void cvt_all_kernel(const float4* __restrict__ Q,
                               const float4* __restrict__ P,
                               const float4* __restrict__ HN)
{
    const int i = blockIdx.x * blockDim.x + threadIdx.x;
    if (i >= N4_TOT) return;
    const float4* src; uint32_t* dst; int j;
    if (i < N4_Q)               { src = Q;  dst = (uint32_t*)Qi;  j = i; }
    else if (i < N4_Q + N4_P)   { src = P;  dst = (uint32_t*)Pi;  j = i - N4_Q; }
    else                        { src = HN; dst = (uint32_t*)HNi; j = i - N4_Q - N4_P; }
    const float4 f = src[j];
    int v0 = max(-127, min(127, __float2int_rn(f.x * SCALE_I8)));
    int v1 = max(-127, min(127, __float2int_rn(f.y * SCALE_I8)));
    int v2 = max(-127, min(127, __float2int_rn(f.z * SCALE_I8)));
    int v3 = max(-127, min(127, __float2int_rn(f.w * SCALE_I8)));
    dst[j] = (uint32_t)(v0 & 0xFF) | ((uint32_t)(v1 & 0xFF) << 8) |
             ((uint32_t)(v2 & 0xFF) << 16) | ((uint32_t)(v3 & 0xFF) << 24);
}

__device__ __forceinline__ void load_B_chunk(uint32_t dst_base, const int8_t* src, int tid)
{
#pragma unroll
    for (int j = 0; j < 4; ++j) {
        const int it = tid + j * 256;          // 1024 segs: 128 rows x 8 segs of 16B
        const int row = it >> 3, ci = it & 7;
        CP_ASYNC16(dst_base + row * RST + ci * 16, src + row * DD + ci * 16);
    }
}

// ---------------- main kernel (R10 + all-resident B; single delta) ----------------
__global__ __launch_bounds__(256) void maxsim_kernel(
    const float* __restrict__ Q,
    const float* __restrict__ P,
    const float* __restrict__ HN)
{
    extern __shared__ char sm[];
    const uint32_t smb = smem_u32(sm);
    const int tid = threadIdx.x;
    const int wid = tid >> 5;
    const int lid = tid & 31;

    // ---- block -> work mapping ----
    const int8_t* aI; const int8_t* bI;
    const float* aF; const float* bF;
    int qrow0, outcol, validM;
    const int bidx = blockIdx.x;
    if (bidx < 2048) {
        const int mt = bidx >> 6, bp = bidx & 63;
        aI = Qi + (size_t)mt * 128 * DD;  aF = Q + (size_t)mt * 128 * DD;
        bI = Pi + (size_t)bp * SD * DD;   bF = P + (size_t)bp * SD * DD;
        qrow0 = mt * 2; outcol = bp; validM = 128;
    } else {
        const int i = bidx - 2048;
        const int b = i >> 2, k = i & 3;
        aI = Qi + (size_t)b * SQ * DD;    aF = Q + (size_t)b * SQ * DD;
        bI = HNi + (size_t)(b * KH + k) * SD * DD;
        bF = HN + (size_t)(b * KH + k) * SD * DD;
        qrow0 = b; outcol = BB + k; validM = 64;
    }

    // ---- prologue: A (group 0) + ALL FOUR B chunks (groups 1..4) ----
#pragma unroll
    for (int j = 0; j < 4; ++j) {
        const int it = tid + j * 256;
        const int row = it >> 3, ci = it & 7;
        if (row < validM)
            CP_ASYNC16(smb + SM_A + row * RST + ci * 16, aI + row * DD + ci * 16);
    }
    if (validM == 64) {  // zero upper A rows for HN blocks
        for (int j = tid; j < 576; j += 256) {
            const int row = 64 + j / 9, ci = j % 9;
            *(uint4*)(sm + SM_A + row * RST + ci * 16) = make_uint4(0, 0, 0, 0);
        }
    }
    CP_COMMIT;
#pragma unroll
    for (int c = 0; c < NCHUNK; ++c) {
        load_B_chunk(smb + SM_B + (uint32_t)c * BSTG, bI + (size_t)c * 128 * DD, tid);
        CP_COMMIT;
    }

    // ---- fragment addressing (R10-validated) ----
    const int wm = wid >> 2, wn = wid & 3;
    const int m0 = wm * 64, n0 = wn * 32;
    const int a_r = (lid & 7) + ((lid >> 3) & 1) * 8;
    const uint32_t a_c = ((lid >> 4) & 1) * 16;
    const uint32_t aBase = smb + SM_A + (uint32_t)((m0 + a_r) * RST) + a_c;
    const int b_r = ((lid >> 4) & 1) * 8 + (lid & 7);
    const uint32_t b_c = ((lid >> 3) & 1) * 16;
    const uint32_t bOff0 = (uint32_t)((n0 + b_r) * RST) + b_c;

    int cfr[4][4][4];
#pragma unroll
    for (int mt = 0; mt < 4; ++mt)
#pragma unroll
        for (int nt = 0; nt < 4; ++nt)
#pragma unroll
            for (int i = 0; i < 4; ++i) cfr[mt][nt][i] = 0;

    uint32_t rmp[4][2];
#pragma unroll
    for (int mt = 0; mt < 4; ++mt) { rmp[mt][0] = 0u; rmp[mt][1] = 0u; }

    // ---- main loop: no mid-loop loads; one barrier per chunk ----
#pragma unroll
    for (int ch = 0; ch < NCHUNK; ++ch) {
        if (ch == 0)      CP_WAIT(3);
        else if (ch == 1) CP_WAIT(2);
        else if (ch == 2) CP_WAIT(1);
        else              CP_WAIT(0);
        __syncthreads();   // cp.async groups are per-thread; publish chunk to all warps

        const uint32_t bb = smb + SM_B + (uint32_t)ch * BSTG;
#pragma unroll
        for (int kk = 0; kk < 4; ++kk) {
            const uint32_t ko = kk * 32;
            uint32_t af[4][4], bf2[2][4];
            LDSM4(af[0], aBase + ko);
            LDSM4(af[1], aBase + 16 * RST + ko);
            LDSM4(af[2], aBase + 32 * RST + ko);
            LDSM4(af[3], aBase + 48 * RST + ko);
            LDSM4(bf2[0], bb + bOff0 + ko);
            LDSM4(bf2[1], bb + bOff0 + 16 * RST + ko);
#pragma unroll
            for (int mt = 0; mt < 4; ++mt) {
                MMAI8(cfr[mt][0], af[mt], bf2[0][0], bf2[0][1]);
                MMAI8(cfr[mt][1], af[mt], bf2[0][2], bf2[0][3]);
                MMAI8(cfr[mt][2], af[mt], bf2[1][0], bf2[1][1]);
                MMAI8(cfr[mt][3], af[mt], bf2[1][2], bf2[1][3]);
            }
        }

        // fold; doc idx = ch*128 + n0 + nt*8 + 2*(lid&3) + j
        const uint32_t base = (uint32_t)(ch * 128 + n0 + 2 * (lid & 3));
#pragma unroll
        for (int mt = 0; mt < 4; ++mt)
#pragma unroll
            for (int nt = 0; nt < 4; ++nt)
#pragma unroll
                for (int h = 0; h < 2; ++h)
#pragma unroll
                    for (int j = 0; j < 2; ++j) {
                        const uint32_t pk = packmax_i(cfr[mt][nt][h * 2 + j], base + nt * 8 + j);
                        rmp[mt][h] = (pk > rmp[mt][h]) ? pk : rmp[mt][h];
                        cfr[mt][nt][h * 2 + j] = 0;
                    }
    }
    __syncthreads();

    // ---- reduce packed max across lane quads, then across wn (R10-identical) ----
    uint32_t* redp = (uint32_t*)(sm + SM_REDP);
#pragma unroll
    for (int mt = 0; mt < 4; ++mt)
#pragma unroll
        for (int h = 0; h < 2; ++h) {
            uint32_t v = rmp[mt][h];
#pragma unroll
            for (int o = 1; o <= 2; o <<= 1) {
                const uint32_t ov = __shfl_xor_sync(0xffffffffu, v, o);
                v = (ov > v) ? ov : v;
            }
            if ((lid & 3) == 0)
                redp[(m0 + mt * 16 + h * 8 + (lid >> 2)) * 4 + wn] = v;
        }
    __syncthreads();

    int* widx = (int*)(sm + SM_WIDX);
    if (tid < 128) {
        uint32_t best = redp[tid * 4];
#pragma unroll
        for (int w = 1; w < 4; ++w) {
            const uint32_t v = redp[tid * 4 + w];
            best = (v > best) ? v : best;
        }
        widx[tid] = (int)(best & 0x1FFu);
    }
    __syncthreads();

    // ---- phase 2: exact fp32 rescore of winners (R10-identical) ----
    float* exsc = (float*)(sm + SM_EXSC);
    {
        const int r = tid >> 1, hf = tid & 1;
        const int rr = (r < validM) ? r : 0;
        const float* qp = aF + (size_t)rr * DD + hf * 64;
        const float* dp = bF + (size_t)widx[rr] * DD + hf * 64;
        float a0 = 0.f, a1 = 0.f, a2 = 0.f, a3 = 0.f;
#pragma unroll
        for (int j = 0; j < 16; ++j) {
            const float4 qv = __ldg((const float4*)(qp + j * 4));
            const float4 dv = __ldg((const float4*)(dp + j * 4));
            a0 = fmaf(qv.x, dv.x, a0);
            a1 = fmaf(qv.y, dv.y, a1);
            a2 = fmaf(qv.z, dv.z, a2);
            a3 = fmaf(qv.w, dv.w, a3);
        }
        float s = (a0 + a1) + (a2 + a3);
        s += __shfl_xor_sync(0xffffffffu, s, 1);
        if (hf == 0 && r < validM) exsc[r] = s;
    }
    __syncthreads();

    // ---- sum 64 row scores per batch ----
    if (wid < (validM >> 6)) {
        float s = exsc[wid * 64 + lid] + exsc[wid * 64 + 32 + lid];
#pragma unroll
        for (int o = 16; o > 0; o >>= 1) s += __shfl_down_sync(0xffffffffu, s, o);
        if (lid == 0) g_scores[qrow0 + wid][outcol] = s;
    }
}

// ---------------- loss kernel (R10-identical) ----------------
__global__ void loss_kernel(float* __restrict__ out)
{
    __shared__ float red[BB];
    const int q = threadIdx.x >> 1, part = threadIdx.x & 1;
    const float* row = &g_scores[q][0];
    const float pos = row[q];

    float m = -INFINITY;
    for (int j = part * 34; j < part * 34 + 34; ++j) m = fmaxf(m, row[j]);
    m = fmaxf(m, __shfl_xor_sync(0xffffffffu, m, 1));
    m = fmaxf(m, pos);

    float sum = (part == 0) ? expf((pos - m) * INV_T) : 0.f;
    for (int j = part * 34; j < part * 34 + 34; ++j) sum += expf((row[j] - m) * INV_T);
    sum += __shfl_xor_sync(0xffffffffu, sum, 1);

    if (part == 0) red[q] = m * INV_T + logf(sum) - pos * INV_T;
    __syncthreads();

    if (threadIdx.x < 32) {
        float s = red[threadIdx.x] + red[threadIdx.x + 32];
#pragma unroll
        for (int o = 16; o > 0; o >>= 1) s += __shfl_down_sync(0xffffffffu, s, o);
        if (threadIdx.x == 0) out[0] = s / (float)BB;
    }
}

extern "C" void kernel_launch(void* const* d_in, const int* in_sizes, int n_in,
                              void* d_out, int out_size)
{
    const float* Q  = (const float*)d_in[0];
    const float* P  = (const float*)d_in[1];
    const float* HN = (const float*)d_in[2];
    (void)in_sizes; (void)n_in; (void)out_size;

    static bool attr_set = false;
    if (!attr_set) {
        cudaFuncSetAttribute(maxsim_kernel,
                             cudaFuncAttributeMaxDynamicSharedMemorySize, SMEM_TOTAL);
        attr_set = true;
    }

    cvt_all_kernel<<<(N4_TOT + 255) / 256, 256>>>(
        (const float4*)Q, (const float4*)P, (const float4*)HN);
    maxsim_kernel<<<2048 + BB * KH, 256, SMEM_TOTAL>>>(Q, P, HN);
    loss_kernel<<<1, 128>>>((float*)d_out);
}